// round 7
// baseline (speedup 1.0000x reference)
#include <cuda_runtime.h>
#include <cuda_bf16.h>
#include <cstdint>
#include <cfloat>

// Problem shape (fixed by the dataset)
#define B_ROWS 4096
#define N_ROWS 32768
#define DIM    512

#define NSLICES 16
#define SLICE_N (N_ROWS / NSLICES)      // 2048
#define BM 128
#define BN 128
#define BK 64                           // K-chunk
#define MTILES (B_ROWS / BM)            // 32
#define NT     (SLICE_N / BN)           // 16 n-tiles per CTA
#define KCHUNKS (DIM / BK)              // 8 chunks per n-tile
#define TOTAL_GC (NT * KCHUNKS)         // 128 flat chunk iterations
#define STAGES 4
#define TOPK_CAP 10
#define NCONTRIB 8                      // per-row thread contributions (2 warpN x 4 lanes)

#define LDSB 144                        // padded smem row stride in bytes (72 bf16)
#define CHUNK_BYTES (BM * LDSB)         // 18432
#define OFF_A 0                         // 8 chunks resident = 147456 B
#define OFF_B (KCHUNKS * CHUNK_BYTES)   // 4 stages = 73728 B
#define SMEM_DYN (OFF_B + STAGES * CHUNK_BYTES)   // 221184 <= 227KB

// ---- device scratch (no cudaMalloc allowed) ----
__device__ __nv_bfloat16 g_Xb[(size_t)B_ROWS * DIM];
__device__ __nv_bfloat16 g_Yb[(size_t)B_ROWS * DIM];
__device__ __nv_bfloat16 g_Zt[(size_t)N_ROWS * DIM];
__device__ __nv_bfloat16 g_Zr[(size_t)N_ROWS * DIM];
__device__ float g_top[(size_t)2 * B_ROWS * NSLICES * NCONTRIB * TOPK_CAP];
__device__ float g_acc[3];   // [0]=dot  [1]=fk0 sum  [2]=fk1 sum

// ---- PTX helpers ----
__device__ __forceinline__ uint32_t smem_u32(const void* p) {
    return (uint32_t)__cvta_generic_to_shared(p);
}
__device__ __forceinline__ void cp_async16(uint32_t dst, const void* src) {
    asm volatile("cp.async.cg.shared.global [%0], [%1], 16;\n" :: "r"(dst), "l"(src));
}
__device__ __forceinline__ void cp_commit() {
    asm volatile("cp.async.commit_group;\n");
}
__device__ __forceinline__ void cp_wait2() {
    asm volatile("cp.async.wait_group 2;\n" ::: "memory");
}
__device__ __forceinline__ void ldm_x4(uint32_t& r0, uint32_t& r1, uint32_t& r2, uint32_t& r3,
                                       uint32_t addr) {
    asm volatile("ldmatrix.sync.aligned.m8n8.x4.shared.b16 {%0,%1,%2,%3}, [%4];\n"
                 : "=r"(r0), "=r"(r1), "=r"(r2), "=r"(r3) : "r"(addr));
}
__device__ __forceinline__ void mma_bf16(float* c, const uint32_t* a, const uint32_t* b) {
    asm volatile(
        "mma.sync.aligned.m16n8k16.row.col.f32.bf16.bf16.f32 "
        "{%0,%1,%2,%3}, {%4,%5,%6,%7}, {%8,%9}, {%0,%1,%2,%3};\n"
        : "+f"(c[0]), "+f"(c[1]), "+f"(c[2]), "+f"(c[3])
        : "r"(a[0]), "r"(a[1]), "r"(a[2]), "r"(a[3]), "r"(b[0]), "r"(b[1]));
}

// ---- tiny kernels ----
__global__ void zero_kernel() {
    if (threadIdx.x < 3) g_acc[threadIdx.x] = 0.0f;
}

__global__ void prep_kernel(const float* __restrict__ Xt, const float* __restrict__ Yt,
                            const float* __restrict__ Zt, const float* __restrict__ Zr) {
    size_t stride = (size_t)gridDim.x * blockDim.x;
    size_t i0 = (size_t)blockIdx.x * blockDim.x + threadIdx.x;
    const size_t nB = (size_t)B_ROWS * DIM;
    const size_t nN = (size_t)N_ROWS * DIM;
    for (size_t i = i0; i < nB; i += stride) {
        g_Xb[i] = __float2bfloat16(Xt[i]);
        g_Yb[i] = __float2bfloat16(Yt[i]);
    }
    for (size_t i = i0; i < nN; i += stride) {
        g_Zt[i] = __float2bfloat16(Zt[i]);
        g_Zr[i] = __float2bfloat16(Zr[i]);
    }
}

__global__ void dot_kernel(const float* __restrict__ X, const float* __restrict__ Y) {
    float s = 0.0f;
    size_t stride = (size_t)gridDim.x * blockDim.x;
    for (size_t i = (size_t)blockIdx.x * blockDim.x + threadIdx.x;
         i < (size_t)B_ROWS * DIM; i += stride)
        s += X[i] * Y[i];
    #pragma unroll
    for (int o = 16; o; o >>= 1) s += __shfl_xor_sync(0xFFFFFFFFu, s, o);
    __shared__ float ws[8];
    if ((threadIdx.x & 31) == 0) ws[threadIdx.x >> 5] = s;
    __syncthreads();
    if (threadIdx.x < 8) {
        float v = ws[threadIdx.x];
        #pragma unroll
        for (int o = 4; o; o >>= 1) v += __shfl_xor_sync(0xFFu, v, o);
        if (threadIdx.x == 0) atomicAdd(&g_acc[0], v);
    }
}

// ---- fused bf16 GEMM (A resident, B streamed) + register top-10 ----
// grid: x = MTILES*NSLICES, y = 2; block: 256 threads (8 warps, warp tile 32x64).
__global__ void __launch_bounds__(256, 1) gemm_topk_kernel() {
    extern __shared__ __align__(16) char dsm[];
    const uint32_t sA = smem_u32(dsm) + OFF_A;
    const uint32_t sB = smem_u32(dsm) + OFF_B;

    const int mat = blockIdx.y;
    const __nv_bfloat16* __restrict__ Amat = mat ? g_Yb : g_Xb;
    const __nv_bfloat16* __restrict__ Zmat = mat ? g_Zr : g_Zt;
    const int mblk  = blockIdx.x % MTILES;
    const int slice = blockIdx.x / MTILES;
    const int m0    = mblk * BM;
    const int nbase = slice * SLICE_N;

    const int tid = threadIdx.x;
    const int lane = tid & 31, wid = tid >> 5;
    const int warpM = wid >> 1, warpN = wid & 1;
    const int g = lane >> 2;

    // --- precomputed fragment row offsets (verified mapping from R5) ---
    uint32_t aoff[2], boff[4];
    #pragma unroll
    for (int mf = 0; mf < 2; ++mf) {
        int row = warpM * 32 + mf * 16 + ((lane >> 3) & 1) * 8 + (lane & 7);
        aoff[mf] = (uint32_t)row * LDSB;
    }
    #pragma unroll
    for (int p = 0; p < 4; ++p) {
        int row = warpN * 64 + p * 16 + ((lane >> 4) & 1) * 8 + (lane & 7);
        boff[p] = (uint32_t)row * LDSB;
    }
    const uint32_t acol = ((lane >> 4) & 1) * 16;   // byte offset of 8-col group
    const uint32_t bcol = ((lane >> 3) & 1) * 16;

    // --- B chunk issue: 4 x 16B segments per thread ---
    auto issueB = [&](int gc) {
        const int nt = gc >> 3, kt = gc & 7;
        const int n0 = nbase + nt * BN;
        const int k0 = kt * BK;
        const uint32_t bb = sB + (uint32_t)(gc & (STAGES - 1)) * CHUNK_BYTES;
        #pragma unroll
        for (int i = 0; i < 4; ++i) {
            int s = i * 256 + tid;
            int r = s >> 3;
            int c8 = (s & 7) * 8;
            cp_async16(bb + (uint32_t)r * LDSB + c8 * 2,
                       Zmat + (size_t)(n0 + r) * DIM + k0 + c8);
        }
    };

    // --- A panel load: 32 x 16B segments per thread, once ---
    #pragma unroll 8
    for (int i = 0; i < 32; ++i) {
        int s = i * 256 + tid;
        int r = s >> 6;
        int col = (s & 63) * 8;
        int chunk = col >> 6;
        int cc = col & 63;
        cp_async16(sA + (uint32_t)chunk * CHUNK_BYTES + (uint32_t)r * LDSB + cc * 2,
                   Amat + (size_t)(m0 + r) * DIM + col);
    }
    cp_commit();                       // group: A
    issueB(0); cp_commit();
    issueB(1); cp_commit();
    issueB(2); cp_commit();

    // --- per-thread top-10 for the 4 owned rows ---
    float top[4][TOPK_CAP];
    float thr[4];
    int mi[4];
    #pragma unroll
    for (int rs = 0; rs < 4; ++rs) {
        thr[rs] = -FLT_MAX; mi[rs] = 0;
        #pragma unroll
        for (int i = 0; i < TOPK_CAP; ++i) top[rs][i] = -FLT_MAX;
    }

    float acc[2][8][4];
    #pragma unroll
    for (int a = 0; a < 2; ++a)
        #pragma unroll
        for (int b = 0; b < 8; ++b)
            #pragma unroll
            for (int c = 0; c < 4; ++c) acc[a][b][c] = 0.0f;

    for (int gc = 0; gc < TOTAL_GC; ++gc) {
        cp_wait2();                 // stage gc ready (A + B0..Bgc complete)
        __syncthreads();
        if (gc + 3 < TOTAL_GC) issueB(gc + 3);
        cp_commit();                // always commit (empty group at tail)

        const int kt = gc & 7;
        const uint32_t abase = sA + (uint32_t)kt * CHUNK_BYTES;
        const uint32_t bbase = sB + (uint32_t)(gc & (STAGES - 1)) * CHUNK_BYTES;

        #pragma unroll
        for (int ks = 0; ks < 4; ++ks) {
            uint32_t afr[2][4];
            #pragma unroll
            for (int mf = 0; mf < 2; ++mf)
                ldm_x4(afr[mf][0], afr[mf][1], afr[mf][2], afr[mf][3],
                       abase + aoff[mf] + ks * 32 + acol);
            uint32_t bfr[8][2];
            #pragma unroll
            for (int p = 0; p < 4; ++p) {
                uint32_t r0, r1, r2, r3;
                ldm_x4(r0, r1, r2, r3, bbase + boff[p] + ks * 32 + bcol);
                bfr[2 * p][0] = r0;     bfr[2 * p][1] = r1;
                bfr[2 * p + 1][0] = r2; bfr[2 * p + 1][1] = r3;
            }
            #pragma unroll
            for (int mf = 0; mf < 2; ++mf)
                #pragma unroll
                for (int nf = 0; nf < 8; ++nf)
                    mma_bf16(acc[mf][nf], afr[mf], bfr[nf]);
        }

        if (kt == 7) {
            // fold accumulators into per-row register top-10s
            #pragma unroll
            for (int mf = 0; mf < 2; ++mf) {
                #pragma unroll
                for (int h = 0; h < 2; ++h) {
                    const int rs = mf * 2 + h;
                    #pragma unroll
                    for (int nf = 0; nf < 8; ++nf) {
                        #pragma unroll
                        for (int c = 0; c < 2; ++c) {
                            float v = acc[mf][nf][h * 2 + c];
                            if (v > thr[rs]) {
                                top[rs][mi[rs]] = v;
                                thr[rs] = top[rs][0]; mi[rs] = 0;
                                #pragma unroll
                                for (int i = 1; i < TOPK_CAP; ++i)
                                    if (top[rs][i] < thr[rs]) { thr[rs] = top[rs][i]; mi[rs] = i; }
                            }
                        }
                    }
                }
            }
            #pragma unroll
            for (int a = 0; a < 2; ++a)
                #pragma unroll
                for (int b = 0; b < 8; ++b)
                    #pragma unroll
                    for (int c = 0; c < 4; ++c) acc[a][b][c] = 0.0f;
        }
    }

    // write candidates: each thread owns 4 rows x 10 values
    const int contrib = warpN * 4 + (lane & 3);
    #pragma unroll
    for (int mf = 0; mf < 2; ++mf) {
        #pragma unroll
        for (int h = 0; h < 2; ++h) {
            const int rs = mf * 2 + h;
            int row = m0 + warpM * 32 + mf * 16 + h * 8 + g;
            size_t base = ((((size_t)mat * B_ROWS + row) * NSLICES + slice) * NCONTRIB
                           + contrib) * TOPK_CAP;
            #pragma unroll
            for (int i = 0; i < TOPK_CAP; ++i) g_top[base + i] = top[rs][i];
        }
    }
}

// merge per-slice/per-thread top-10s into global top-k per row, sum, reduce
__global__ void merge_kernel(const int* __restrict__ knn) {
    int t = blockIdx.x * blockDim.x + threadIdx.x;
    if (t >= 2 * B_ROWS) return;
    int k = *knn;
    if (k > TOPK_CAP) k = TOPK_CAP;
    if (k < 1) k = 1;
    const float* src = g_top + (size_t)t * NSLICES * NCONTRIB * TOPK_CAP;
    float best[TOPK_CAP];
    #pragma unroll
    for (int i = 0; i < TOPK_CAP; ++i) best[i] = -FLT_MAX;
    float thr = -FLT_MAX;
    int mi = 0;
    for (int j = 0; j < NSLICES * NCONTRIB * TOPK_CAP; ++j) {
        float v = src[j];
        if (v > thr) {
            best[mi] = v;
            thr = best[0]; mi = 0;
            for (int i = 1; i < k; ++i)
                if (best[i] < thr) { thr = best[i]; mi = i; }
        }
    }
    float s = 0.0f;
    for (int i = 0; i < k; ++i) s += best[i];
    int mat = t / B_ROWS;
    atomicAdd(&g_acc[1 + mat], s);
}

__global__ void final_kernel(float* __restrict__ out, const int* __restrict__ knn) {
    int k = *knn;
    if (k > TOPK_CAP) k = TOPK_CAP;
    if (k < 1) k = 1;
    // f = 2*dot - fk0 - fk1 ; out = -f/B = (fk0 + fk1 - 2*dot)/B
    out[0] = ((g_acc[1] + g_acc[2]) / (float)k - 2.0f * g_acc[0]) / (float)B_ROWS;
}

extern "C" void kernel_launch(void* const* d_in, const int* in_sizes, int n_in,
                              void* d_out, int out_size) {
    (void)in_sizes; (void)n_in; (void)out_size;
    // metadata order: X_src, X_trans, Y_tgt, Z_src, Z_trans, Z_tgt, knn
    const float* Xt = (const float*)d_in[1];
    const float* Yt = (const float*)d_in[2];
    const float* Zr = (const float*)d_in[4];
    const float* Zt = (const float*)d_in[5];
    const int* knn  = (const int*)d_in[6];
    float* out = (float*)d_out;

    cudaFuncSetAttribute(gemm_topk_kernel,
                         cudaFuncAttributeMaxDynamicSharedMemorySize, SMEM_DYN);

    zero_kernel<<<1, 32>>>();
    prep_kernel<<<2048, 256>>>(Xt, Yt, Zt, Zr);
    dot_kernel<<<1024, 256>>>(Xt, Yt);
    dim3 grid(MTILES * NSLICES, 2);
    gemm_topk_kernel<<<grid, 256, SMEM_DYN>>>();
    merge_kernel<<<(2 * B_ROWS + 255) / 256, 256>>>(knn);
    final_kernel<<<1, 1>>>(out, knn);
}

// round 8
// speedup vs baseline: 1.7067x; 1.7067x over previous
#include <cuda_runtime.h>
#include <cuda_bf16.h>
#include <cstdint>
#include <cfloat>

// Problem shape (fixed by the dataset)
#define B_ROWS 4096
#define N_ROWS 32768
#define DIM    512

#define NSLICES 16
#define SLICE_N (N_ROWS / NSLICES)      // 2048
#define BM 128
#define BN 128
#define BK 32                           // K-chunk
#define MTILES (B_ROWS / BM)            // 32
#define NT     (SLICE_N / BN)           // 16 n-tiles per CTA
#define KCHUNKS (DIM / BK)              // 16 chunks per n-tile
#define TOTAL_GC (NT * KCHUNKS)         // 256 flat chunk iterations
#define STAGES 4
#define TOPK_CAP 10
#define NCONTRIB 8                      // per-row thread contributions (2 warpN x 4 lanes)

// SW64-swizzled 64B rows: stage = A(128*64) + B(128*64) = 16KB
#define STAGE_BYTES 16384
#define OFF_TOP (STAGES * STAGE_BYTES)              // 65536
#define SMEM_DYN (OFF_TOP + 4 * TOPK_CAP * 256 * 4) // + 40KB topk = 106496

// ---- device scratch (no cudaMalloc allowed) ----
__device__ __nv_bfloat16 g_Xb[(size_t)B_ROWS * DIM];
__device__ __nv_bfloat16 g_Yb[(size_t)B_ROWS * DIM];
__device__ __nv_bfloat16 g_Zt[(size_t)N_ROWS * DIM];
__device__ __nv_bfloat16 g_Zr[(size_t)N_ROWS * DIM];
__device__ float g_top[(size_t)2 * B_ROWS * NSLICES * NCONTRIB * TOPK_CAP];
__device__ float g_acc[3];   // [0]=dot  [1]=fk0 sum  [2]=fk1 sum

// ---- PTX helpers ----
__device__ __forceinline__ uint32_t smem_u32(const void* p) {
    return (uint32_t)__cvta_generic_to_shared(p);
}
__device__ __forceinline__ void cp_async16(uint32_t dst, const void* src) {
    asm volatile("cp.async.cg.shared.global [%0], [%1], 16;\n" :: "r"(dst), "l"(src));
}
__device__ __forceinline__ void cp_commit() {
    asm volatile("cp.async.commit_group;\n");
}
__device__ __forceinline__ void cp_wait2() {
    asm volatile("cp.async.wait_group 2;\n" ::: "memory");
}
__device__ __forceinline__ void ldm_x4(uint32_t& r0, uint32_t& r1, uint32_t& r2, uint32_t& r3,
                                       uint32_t addr) {
    asm volatile("ldmatrix.sync.aligned.m8n8.x4.shared.b16 {%0,%1,%2,%3}, [%4];\n"
                 : "=r"(r0), "=r"(r1), "=r"(r2), "=r"(r3) : "r"(addr));
}
__device__ __forceinline__ void mma_bf16(float* c, const uint32_t* a, const uint32_t* b) {
    asm volatile(
        "mma.sync.aligned.m16n8k16.row.col.f32.bf16.bf16.f32 "
        "{%0,%1,%2,%3}, {%4,%5,%6,%7}, {%8,%9}, {%0,%1,%2,%3};\n"
        : "+f"(c[0]), "+f"(c[1]), "+f"(c[2]), "+f"(c[3])
        : "r"(a[0]), "r"(a[1]), "r"(a[2]), "r"(a[3]), "r"(b[0]), "r"(b[1]));
}

// ---- tiny kernels ----
__global__ void zero_kernel() {
    if (threadIdx.x < 3) g_acc[threadIdx.x] = 0.0f;
}

__global__ void prep_kernel(const float* __restrict__ Xt, const float* __restrict__ Yt,
                            const float* __restrict__ Zt, const float* __restrict__ Zr) {
    size_t stride = (size_t)gridDim.x * blockDim.x;
    size_t i0 = (size_t)blockIdx.x * blockDim.x + threadIdx.x;
    const size_t nB = (size_t)B_ROWS * DIM;
    const size_t nN = (size_t)N_ROWS * DIM;
    for (size_t i = i0; i < nB; i += stride) {
        g_Xb[i] = __float2bfloat16(Xt[i]);
        g_Yb[i] = __float2bfloat16(Yt[i]);
    }
    for (size_t i = i0; i < nN; i += stride) {
        g_Zt[i] = __float2bfloat16(Zt[i]);
        g_Zr[i] = __float2bfloat16(Zr[i]);
    }
}

__global__ void dot_kernel(const float* __restrict__ X, const float* __restrict__ Y) {
    float s = 0.0f;
    size_t stride = (size_t)gridDim.x * blockDim.x;
    for (size_t i = (size_t)blockIdx.x * blockDim.x + threadIdx.x;
         i < (size_t)B_ROWS * DIM; i += stride)
        s += X[i] * Y[i];
    #pragma unroll
    for (int o = 16; o; o >>= 1) s += __shfl_xor_sync(0xFFFFFFFFu, s, o);
    __shared__ float ws[8];
    if ((threadIdx.x & 31) == 0) ws[threadIdx.x >> 5] = s;
    __syncthreads();
    if (threadIdx.x < 8) {
        float v = ws[threadIdx.x];
        #pragma unroll
        for (int o = 4; o; o >>= 1) v += __shfl_xor_sync(0xFFu, v, o);
        if (threadIdx.x == 0) atomicAdd(&g_acc[0], v);
    }
}

// ---- fused bf16 GEMM (A+B streamed, SW64 swizzle) + smem-backed top-10 ----
// grid: x = MTILES*NSLICES, y = 2; block: 256 threads (8 warps, warp tile 32x64).
__global__ void __launch_bounds__(256, 2) gemm_topk_kernel() {
    extern __shared__ __align__(16) char dsm[];
    const uint32_t sbase = smem_u32(dsm);
    float* sTop = (float*)(dsm + OFF_TOP);   // [4*10][256] thread-private columns

    const int mat = blockIdx.y;
    const __nv_bfloat16* __restrict__ Amat = mat ? g_Yb : g_Xb;
    const __nv_bfloat16* __restrict__ Zmat = mat ? g_Zr : g_Zt;
    const int mblk  = blockIdx.x % MTILES;
    const int slice = blockIdx.x / MTILES;
    const int m0    = mblk * BM;
    const int nbase = slice * SLICE_N;

    const int tid = threadIdx.x;
    const int lane = tid & 31, wid = tid >> 5;
    const int warpM = wid >> 1, warpN = wid & 1;
    const int g = lane >> 2;

    // --- fragment smem offsets with SW64 swizzle (64B rows) ---
    // swz64(r*64 + c) = r*64 + (c ^ ((r*8)&0x30)) for c < 64
    const uint32_t acol = ((lane >> 4) & 1) * 16;
    const uint32_t bcol = ((lane >> 3) & 1) * 16;
    uint32_t aoff[2][2], boff[4][2];
    #pragma unroll
    for (int mf = 0; mf < 2; ++mf) {
        uint32_t row = warpM * 32 + mf * 16 + ((lane >> 3) & 1) * 8 + (lane & 7);
        uint32_t x = (row * 8) & 0x30;
        #pragma unroll
        for (int ks = 0; ks < 2; ++ks)
            aoff[mf][ks] = row * 64 + ((ks * 32 + acol) ^ x);
    }
    #pragma unroll
    for (int p = 0; p < 4; ++p) {
        uint32_t row = warpN * 64 + p * 16 + ((lane >> 4) & 1) * 8 + (lane & 7);
        uint32_t x = (row * 8) & 0x30;
        #pragma unroll
        for (int ks = 0; ks < 2; ++ks)
            boff[p][ks] = row * 64 + ((ks * 32 + bcol) ^ x) + 8192;  // B half of stage
    }

    // --- chunk issue: 2 A-segs + 2 B-segs of 16B per thread ---
    auto issue = [&](int gc) {
        const int nt = gc >> 4, kt = gc & 15;
        const int n0 = nbase + nt * BN;
        const int k0 = kt * BK;
        const uint32_t st = sbase + (uint32_t)(gc & (STAGES - 1)) * STAGE_BYTES;
        #pragma unroll
        for (int i = 0; i < 2; ++i) {
            int s = i * 256 + tid;                 // 0..511
            uint32_t r = (uint32_t)(s >> 2);
            uint32_t c16 = (uint32_t)(s & 3) * 16; // byte col
            uint32_t dsto = r * 64 + (c16 ^ ((r * 8) & 0x30));
            int ce = (s & 3) * 8;                  // elem col
            cp_async16(st + dsto, Amat + (size_t)(m0 + r) * DIM + k0 + ce);
            cp_async16(st + 8192 + dsto, Zmat + (size_t)(n0 + r) * DIM + k0 + ce);
        }
    };

    // init smem top-k columns
    #pragma unroll
    for (int i = 0; i < 4 * TOPK_CAP; ++i) sTop[i * 256 + tid] = -FLT_MAX;
    float thr[4];
    int mi[4];
    #pragma unroll
    for (int rs = 0; rs < 4; ++rs) { thr[rs] = -FLT_MAX; mi[rs] = 0; }

    issue(0); cp_commit();
    issue(1); cp_commit();
    issue(2); cp_commit();

    float acc[2][8][4];
    #pragma unroll
    for (int a = 0; a < 2; ++a)
        #pragma unroll
        for (int b = 0; b < 8; ++b)
            #pragma unroll
            for (int c = 0; c < 4; ++c) acc[a][b][c] = 0.0f;

    for (int gc = 0; gc < TOTAL_GC; ++gc) {
        cp_wait2();
        __syncthreads();
        if (gc + 3 < TOTAL_GC) issue(gc + 3);
        cp_commit();

        const uint32_t st = sbase + (uint32_t)(gc & (STAGES - 1)) * STAGE_BYTES;
        #pragma unroll
        for (int ks = 0; ks < 2; ++ks) {
            uint32_t afr[2][4];
            #pragma unroll
            for (int mf = 0; mf < 2; ++mf)
                ldm_x4(afr[mf][0], afr[mf][1], afr[mf][2], afr[mf][3], st + aoff[mf][ks]);
            uint32_t bfr[8][2];
            #pragma unroll
            for (int p = 0; p < 4; ++p) {
                uint32_t r0, r1, r2, r3;
                ldm_x4(r0, r1, r2, r3, st + boff[p][ks]);
                bfr[2 * p][0] = r0;     bfr[2 * p][1] = r1;
                bfr[2 * p + 1][0] = r2; bfr[2 * p + 1][1] = r3;
            }
            #pragma unroll
            for (int mf = 0; mf < 2; ++mf)
                #pragma unroll
                for (int nf = 0; nf < 8; ++nf)
                    mma_bf16(acc[mf][nf], afr[mf], bfr[nf]);
        }

        if ((gc & 15) == 15) {
            // fold accumulators into smem-backed per-row top-10s
            #pragma unroll
            for (int mf = 0; mf < 2; ++mf) {
                #pragma unroll
                for (int h = 0; h < 2; ++h) {
                    const int rs = mf * 2 + h;
                    float t = thr[rs];
                    int m = mi[rs];
                    #pragma unroll
                    for (int nf = 0; nf < 8; ++nf) {
                        #pragma unroll
                        for (int c = 0; c < 2; ++c) {
                            float v = acc[mf][nf][h * 2 + c];
                            if (v > t) {
                                sTop[(rs * TOPK_CAP + m) * 256 + tid] = v;
                                t = FLT_MAX; m = 0;
                                #pragma unroll
                                for (int i = 0; i < TOPK_CAP; ++i) {
                                    float u = sTop[(rs * TOPK_CAP + i) * 256 + tid];
                                    if (u < t) { t = u; m = i; }
                                }
                            }
                        }
                    }
                    thr[rs] = t; mi[rs] = m;
                }
            }
            #pragma unroll
            for (int a = 0; a < 2; ++a)
                #pragma unroll
                for (int b = 0; b < 8; ++b)
                    #pragma unroll
                    for (int c = 0; c < 4; ++c) acc[a][b][c] = 0.0f;
        }
    }

    // write candidates: each thread owns 4 rows x 10 values
    const int contrib = warpN * 4 + (lane & 3);
    #pragma unroll
    for (int mf = 0; mf < 2; ++mf) {
        #pragma unroll
        for (int h = 0; h < 2; ++h) {
            const int rs = mf * 2 + h;
            int row = m0 + warpM * 32 + mf * 16 + h * 8 + g;
            size_t base = ((((size_t)mat * B_ROWS + row) * NSLICES + slice) * NCONTRIB
                           + contrib) * TOPK_CAP;
            #pragma unroll
            for (int i = 0; i < TOPK_CAP; ++i)
                g_top[base + i] = sTop[(rs * TOPK_CAP + i) * 256 + tid];
        }
    }
}

// merge per-slice/per-thread top-10s into global top-k per row, sum, reduce
__global__ void merge_kernel(const int* __restrict__ knn) {
    int t = blockIdx.x * blockDim.x + threadIdx.x;
    if (t >= 2 * B_ROWS) return;
    int k = *knn;
    if (k > TOPK_CAP) k = TOPK_CAP;
    if (k < 1) k = 1;
    const float* src = g_top + (size_t)t * NSLICES * NCONTRIB * TOPK_CAP;
    float best[TOPK_CAP];
    #pragma unroll
    for (int i = 0; i < TOPK_CAP; ++i) best[i] = -FLT_MAX;
    float thr = -FLT_MAX;
    int mi = 0;
    for (int j = 0; j < NSLICES * NCONTRIB * TOPK_CAP; ++j) {
        float v = src[j];
        if (v > thr) {
            best[mi] = v;
            thr = best[0]; mi = 0;
            for (int i = 1; i < k; ++i)
                if (best[i] < thr) { thr = best[i]; mi = i; }
        }
    }
    float s = 0.0f;
    for (int i = 0; i < k; ++i) s += best[i];
    int mat = t / B_ROWS;
    atomicAdd(&g_acc[1 + mat], s);
}

__global__ void final_kernel(float* __restrict__ out, const int* __restrict__ knn) {
    int k = *knn;
    if (k > TOPK_CAP) k = TOPK_CAP;
    if (k < 1) k = 1;
    // f = 2*dot - fk0 - fk1 ; out = -f/B = (fk0 + fk1 - 2*dot)/B
    out[0] = ((g_acc[1] + g_acc[2]) / (float)k - 2.0f * g_acc[0]) / (float)B_ROWS;
}

extern "C" void kernel_launch(void* const* d_in, const int* in_sizes, int n_in,
                              void* d_out, int out_size) {
    (void)in_sizes; (void)n_in; (void)out_size;
    // metadata order: X_src, X_trans, Y_tgt, Z_src, Z_trans, Z_tgt, knn
    const float* Xt = (const float*)d_in[1];
    const float* Yt = (const float*)d_in[2];
    const float* Zr = (const float*)d_in[4];
    const float* Zt = (const float*)d_in[5];
    const int* knn  = (const int*)d_in[6];
    float* out = (float*)d_out;

    cudaFuncSetAttribute(gemm_topk_kernel,
                         cudaFuncAttributeMaxDynamicSharedMemorySize, SMEM_DYN);

    zero_kernel<<<1, 32>>>();
    prep_kernel<<<2048, 256>>>(Xt, Yt, Zt, Zr);
    dot_kernel<<<1024, 256>>>(Xt, Yt);
    dim3 grid(MTILES * NSLICES, 2);
    gemm_topk_kernel<<<grid, 256, SMEM_DYN>>>();
    merge_kernel<<<(2 * B_ROWS + 255) / 256, 256>>>(knn);
    final_kernel<<<1, 1>>>(out, knn);
}